// round 13
// baseline (speedup 1.0000x reference)
#include <cuda_runtime.h>
#include <cstdint>

// image: [64, 3, 512, 512] fp32; mask [64,64] bool-as-int32 (rate ~0.5).
// out = where(mask8x8, -1.0f, image).
//
// FINAL (champion, reproduced 3x at 61.92us wall / ~54.9us kernel,
// ~96% of the 334MB @ 6.34TB/s bandwidth floor):
// UNROLL=4 (MLP=4 per thread), 256 threads/block, exact grid (no tail),
// sector-predicated __ldcg image loads (fully-masked 128B lines never
// fetched; L2-only, no L1 alloc), __stcs evict-first streaming stores.

#define W4 128            // float4s per row (W=512)
#define UNROLL 4

__global__ void __launch_bounds__(256) grid_crop_kernel(
    const float4* __restrict__ img,
    const int* __restrict__ sw,      // [64,64] bool-as-int32
    float4* __restrict__ out)
{
    int base = blockIdx.x * (256 * UNROLL) + threadIdx.x;

    int idx[UNROLL];
    int m[UNROLL];
    float4 v[UNROLL];

    // Mask lookups (L1-resident, broadcast across 8 adjacent threads).
    #pragma unroll
    for (int k = 0; k < UNROLL; k++) {
        idx[k] = base + k * 256;
        int w4 = idx[k] & (W4 - 1);          // 0..127
        int h  = (idx[k] >> 7) & 511;        // 0..511
        m[k] = __ldg(&sw[((h >> 3) << 6) | (w4 >> 1)]);
    }

    // Predicated L2-only loads: fully-masked 128B lines never fetched.
    #pragma unroll
    for (int k = 0; k < UNROLL; k++) {
        v[k] = make_float4(-1.0f, -1.0f, -1.0f, -1.0f);
        if (!m[k]) v[k] = __ldcg(&img[idx[k]]);
    }

    // Evict-first streaming stores.
    #pragma unroll
    for (int k = 0; k < UNROLL; k++) {
        __stcs(&out[idx[k]], v[k]);
    }
}

extern "C" void kernel_launch(void* const* d_in, const int* in_sizes, int n_in,
                              void* d_out, int out_size)
{
    const void* p_img = d_in[0];
    const void* p_sw  = d_in[1];
    if (n_in >= 2 && in_sizes[0] < in_sizes[1]) {
        p_img = d_in[1];
        p_sw  = d_in[0];
    }

    const float4* img = (const float4*)p_img;
    const int* sw = (const int*)p_sw;
    float4* out = (float4*)d_out;

    int n4 = out_size / 4;                      // 12,582,912
    int blocks = n4 / (256 * UNROLL);           // 12,288 exact
    grid_crop_kernel<<<blocks, 256>>>(img, sw, out);
}